// round 13
// baseline (speedup 1.0000x reference)
#include <cuda_runtime.h>
#include <math.h>
#include <stdint.h>

#define B  4
#define NN 65536
#define KK 16
#define DD 32
#define NP 16384

// scratch
__device__ float  g_pool_t[(size_t)B * NN * DD];    // 33.6 MB  [b][n][d]
__device__ float  g_interp_t[(size_t)B * NP * DD];  //  8.4 MB  [b][np][d]
__device__ float4 g_xyz4[(size_t)B * NN];           //  4.2 MB  padded xyz

#define TB1   (B * (NN / 32))      // 8192  transpose feat_pool tiles
#define TB2   (B * (NP / 32))      // 2048  transpose feat_interp tiles
#define XB    (B * NN / 256)       // 1024  xyz padding blocks
#define RELB  (B * NN * KK / 512)  // 8192  rel blocks (512 pairs each)
#define POOLB (B * (NP / 32))      // 2048  pool blocks
#define IB4   (B * (NN / 128))     // 2048  interp blocks (4 tiles each)

__device__ __forceinline__ uint32_t smem_u32(const void* p) {
    uint32_t a;
    asm("{ .reg .u64 t; cvta.to.shared.u64 t, %1; cvt.u32.u64 %0, t; }"
        : "=r"(a) : "l"(p));
    return a;
}

__device__ __forceinline__ float4 shfl_xor1_f4(float4 v) {
    float4 r;
    r.x = __shfl_xor_sync(0xFFFFFFFFu, v.x, 1);
    r.y = __shfl_xor_sync(0xFFFFFFFFu, v.y, 1);
    r.z = __shfl_xor_sync(0xFFFFFFFFu, v.z, 1);
    r.w = __shfl_xor_sync(0xFFFFFFFFu, v.w, 1);
    return r;
}

// ============ kX: pad xyz [B*N,3] -> float4 ============
__global__ void __launch_bounds__(256) kX(const float* __restrict__ xyz) {
    __shared__ float s[768];
    int tid = threadIdx.x;
    int p0 = blockIdx.x * 256;
    const float* src = xyz + (size_t)p0 * 3;
    s[tid]       = __ldcs(&src[tid]);
    s[256 + tid] = __ldcs(&src[256 + tid]);
    s[512 + tid] = __ldcs(&src[512 + tid]);
    __syncthreads();
    g_xyz4[p0 + tid] = make_float4(s[tid * 3], s[tid * 3 + 1], s[tid * 3 + 2], 0.0f);
}

// ============ kT: transposes [B,32,M] -> [B,M,32] ============
__global__ void __launch_bounds__(256) kT(
    const float* __restrict__ feat_pool,
    const float* __restrict__ feat_interp)
{
    __shared__ float sm[32 * 33];
    float (*tile)[33] = (float (*)[33])sm;
    int tid = threadIdx.x;
    int tb = blockIdx.x;
    const float* in;
    float* outp;
    int M;
    if (tb < TB1) { in = feat_pool;   outp = g_pool_t;   M = NN; }
    else          { in = feat_interp; outp = g_interp_t; M = NP; tb -= TB1; }
    int mb = M / 32;
    int b  = tb / mb;
    int m0 = (tb - b * mb) * 32;
    int tx = tid & 31, ty = tid >> 5;
#pragma unroll
    for (int rr = 0; rr < 4; rr++) {
        int d = ty + 8 * rr;
        tile[d][tx] = __ldcs(&in[((size_t)(b * DD + d)) * M + m0 + tx]);
    }
    __syncthreads();
    // vectorized store: thread (m = tid>>3, c = tid&7) -> one float4
    int m = tid >> 3;
    int c = tid & 7;
    float4 v = make_float4(tile[4 * c + 0][m], tile[4 * c + 1][m],
                           tile[4 * c + 2][m], tile[4 * c + 3][m]);
    float4* o4 = (float4*)(outp + ((size_t)(b * M + m0)) * DD);
    o4[tid] = v;
}

// ============ kRel: 512 pairs/block, conflict-free staging + TMA ============
__global__ void __launch_bounds__(256) kRel(
    const int* __restrict__ nidx,
    float* __restrict__ out_rel)
{
    __shared__ __align__(16) float smem[5120];   // 20 KB
    int tid = threadIdx.x;
    int rb = blockIdx.x;                // 0..8191
    int pbase = rb * 512;
    int b   = pbase >> 20;              // N*K = 2^20
    int bb  = b << 16;
    int nkb = pbase & 0xFFFFF;
    int t2  = tid * 2;

    int2 ii = __ldcs((const int2*)(nidx + pbase + t2));
    float4 Q0 = __ldg(&g_xyz4[bb + ii.x]);
    float4 Q1 = __ldg(&g_xyz4[bb + ii.y]);
    // pairs (2t, 2t+1) share n since t2 is even and K=16
    float4 P  = __ldg(&g_xyz4[bb + ((nkb + t2) >> 4)]);

    float rx0 = P.x - Q0.x, ry0 = P.y - Q0.y, rz0 = P.z - Q0.z;
    float d0 = sqrtf(rx0 * rx0 + ry0 * ry0 + rz0 * rz0);
    float rx1 = P.x - Q1.x, ry1 = P.y - Q1.y, rz1 = P.z - Q1.z;
    float d1 = sqrtf(rx1 * rx1 + ry1 * ry1 + rz1 * rz1);

    // thread t owns output float4 slots 5t..5t+4:
    float4 v0 = make_float4(d0, rx0, ry0, rz0);
    float4 v1 = make_float4(P.x, P.y, P.z, Q0.x);
    float4 v2 = make_float4(Q0.y, Q0.z, d1, rx1);
    float4 v3 = make_float4(ry1, rz1, P.x, P.y);
    float4 v4 = make_float4(P.z, Q1.x, Q1.y, Q1.z);

    // exchange v1, v3 with partner thread (xor 1)
    float4 xv1 = shfl_xor1_f4(v1);
    float4 xv3 = shfl_xor1_f4(v3);

    // interleaved conflict-free stores: thread-pair q = tid>>1 owns slots
    // 10q..10q+9; even thread writes slots 10q+{0,2,4,6,8} with
    // {v0,v2,v4,partner.v1,partner.v3}, odd writes 10q+{1,3,5,7,9} with
    // {partner.v1,partner.v3,v0,v2,v4}. Each STS.128 phase hits disjoint
    // bank quads -> 4 wavefronts (minimum).
    float4 w0, w1, w2, w3, w4;
    if (tid & 1) { w0 = xv1; w1 = xv3; w2 = v0; w3 = v2; w4 = v4; }
    else         { w0 = v0;  w1 = v2;  w2 = v4; w3 = xv1; w4 = xv3; }
    float4* s4 = (float4*)smem;
    int base = 10 * (tid >> 1) + (tid & 1);
    s4[base + 0] = w0;
    s4[base + 2] = w1;
    s4[base + 4] = w2;
    s4[base + 6] = w3;
    s4[base + 8] = w4;
    __syncthreads();

    asm volatile("fence.proxy.async.shared::cta;" ::: "memory");
    if (tid == 0) {
        uint32_t sa = smem_u32(smem);
        float* gp = out_rel + (size_t)rb * 5120;
        asm volatile(
            "cp.async.bulk.global.shared::cta.bulk_group [%0], [%1], %2;"
            :: "l"(gp), "r"(sa), "n"(20480) : "memory");
        asm volatile("cp.async.bulk.commit_group;" ::: "memory");
        asm volatile("cp.async.bulk.wait_group.read 0;" ::: "memory");
    }
    __syncthreads();
}

// ============ kPI: pool + interp (bid&1) ============
__global__ void __launch_bounds__(256) kPI(
    const int* __restrict__ pool_idx,
    const int* __restrict__ interp_idx,
    float* __restrict__ out_pool,
    float* __restrict__ out_interp)
{
    __shared__ float smem[4 * 32 * 33];
    int bid = blockIdx.x;
    int tid = threadIdx.x;
    int lane = tid & 31, w = tid >> 5;
    int row  = w * 4 + (lane >> 3);
    int dv   = lane & 7;
    int r = bid & 1;
    int g = bid >> 1;

    if (r == 0) {
        // -------- gather-max pooling --------
        float (*tile)[33] = (float (*)[33])smem;
        int b   = g / (NP / 32);
        int np0 = (g - b * (NP / 32)) * 32;
        const int* ip = pool_idx + (b * NP + np0 + row) * KK;
        const float* basep = g_pool_t + (size_t)b * NN * DD;

        float4 m = make_float4(-INFINITY, -INFINITY, -INFINITY, -INFINITY);
#pragma unroll
        for (int kc = 0; kc < 4; kc++) {
            int4 q = __ldcs((const int4*)ip + kc);
            int qq[4] = {q.x, q.y, q.z, q.w};
#pragma unroll
            for (int j = 0; j < 4; j++) {
                float4 v = *(const float4*)(basep + qq[j] * DD + dv * 4);
                m.x = fmaxf(m.x, v.x); m.y = fmaxf(m.y, v.y);
                m.z = fmaxf(m.z, v.z); m.w = fmaxf(m.w, v.w);
            }
        }
        tile[row][dv * 4 + 0] = m.x;
        tile[row][dv * 4 + 1] = m.y;
        tile[row][dv * 4 + 2] = m.z;
        tile[row][dv * 4 + 3] = m.w;
        __syncthreads();
#pragma unroll
        for (int rr = 0; rr < 4; rr++) {
            int d = w + 8 * rr;
            __stcs(&out_pool[(size_t)(b * DD + d) * NP + np0 + lane], tile[lane][d]);
        }
    } else {
        // -------- nearest interpolation: 4 tiles / block --------
        float (*tile)[33] = (float (*)[33])smem;
        int b  = g / (NN / 128);
        int u0 = (g - b * (NN / 128)) * 128;

        float4 v[4];
#pragma unroll
        for (int it = 0; it < 4; it++) {
            int i = __ldg(&interp_idx[b * NN + u0 + it * 32 + row]);
            v[it] = *(const float4*)(g_interp_t + ((size_t)(b * NP + i)) * DD + dv * 4);
        }
#pragma unroll
        for (int it = 0; it < 4; it++) {
            tile[it * 32 + row][dv * 4 + 0] = v[it].x;
            tile[it * 32 + row][dv * 4 + 1] = v[it].y;
            tile[it * 32 + row][dv * 4 + 2] = v[it].z;
            tile[it * 32 + row][dv * 4 + 3] = v[it].w;
        }
        __syncthreads();
#pragma unroll
        for (int it = 0; it < 4; it++) {
#pragma unroll
            for (int rr = 0; rr < 4; rr++) {
                int d = w + 8 * rr;
                __stcs(&out_interp[(size_t)(b * DD + d) * NN + u0 + it * 32 + lane],
                       tile[it * 32 + lane][d]);
            }
        }
    }
}

extern "C" void kernel_launch(void* const* d_in, const int* in_sizes, int n_in,
                              void* d_out, int out_size) {
    const float* xyz         = (const float*)d_in[0];   // [B,N,3]
    const int*   neigh_idx   = (const int*)  d_in[1];   // [B,N,K]
    const float* feat_pool   = (const float*)d_in[2];   // [B,32,N,1]
    const int*   pool_idx    = (const int*)  d_in[3];   // [B,Np,K]
    const float* feat_interp = (const float*)d_in[4];   // [B,32,Np,1]
    const int*   interp_idx  = (const int*)  d_in[5];   // [B,N,1]

    float* out = (float*)d_out;
    float* out_rel    = out;                                // B*N*K*10
    float* out_pool   = out + (size_t)B * NN * KK * 10;     // B*32*Np
    float* out_interp = out_pool + (size_t)B * DD * NP;     // B*32*N

    // one-time side stream + events (host-side objects; no device allocs)
    static cudaStream_t s2 = nullptr;
    static cudaEvent_t evFork = nullptr, evJoin = nullptr;
    if (s2 == nullptr) {
        cudaStreamCreateWithFlags(&s2, cudaStreamNonBlocking);
        cudaEventCreateWithFlags(&evFork, cudaEventDisableTiming);
        cudaEventCreateWithFlags(&evJoin, cudaEventDisableTiming);
    }

    // fork: branch B (transposes -> pool/interp) runs parallel to branch A
    cudaEventRecord(evFork, 0);
    cudaStreamWaitEvent(s2, evFork, 0);

    // branch B on s2
    kT <<<TB1 + TB2, 256, 0, s2>>>(feat_pool, feat_interp);
    kPI<<<POOLB + IB4, 256, 0, s2>>>(pool_idx, interp_idx, out_pool, out_interp);
    cudaEventRecord(evJoin, s2);

    // branch A on default stream
    kX  <<<XB, 256>>>(xyz);
    kRel<<<RELB, 256>>>(neigh_idx, out_rel);

    // join
    cudaStreamWaitEvent(0, evJoin, 0);
}

// round 14
// speedup vs baseline: 1.0278x; 1.0278x over previous
#include <cuda_runtime.h>
#include <math.h>
#include <stdint.h>

#define B  4
#define NN 65536
#define KK 16
#define DD 32
#define NP 16384

// scratch
__device__ float  g_pool_t[(size_t)B * NN * DD];    // 33.6 MB  [b][n][d]
__device__ float  g_interp_t[(size_t)B * NP * DD];  //  8.4 MB  [b][np][d]
__device__ float4 g_xyz4[(size_t)B * NN];           //  4.2 MB  padded xyz

#define TB1   (B * (NN / 128))     // 2048  transpose feat_pool tiles (32x128)
#define TB2   (B * (NP / 128))     // 512   transpose feat_interp tiles
#define XB    (B * NN / 256)       // 1024  xyz padding blocks
#define RELB  (B * NN * KK / 512)  // 8192  rel blocks (512 pairs each)
#define POOLB (B * (NP / 32))      // 2048  pool blocks
#define IB4   (B * (NN / 128))     // 2048  interp blocks (4 tiles each)

__device__ __forceinline__ uint32_t smem_u32(const void* p) {
    uint32_t a;
    asm("{ .reg .u64 t; cvta.to.shared.u64 t, %1; cvt.u32.u64 %0, t; }"
        : "=r"(a) : "l"(p));
    return a;
}

// ============ kX: pad xyz [B*N,3] -> float4, float4 loads ============
__global__ void __launch_bounds__(256) kX(const float* __restrict__ xyz) {
    __shared__ float s[768];
    int tid = threadIdx.x;
    int p0 = blockIdx.x * 256;
    const float4* src = (const float4*)(xyz + (size_t)p0 * 3);  // 192 float4
    if (tid < 192) {
        float4 v = __ldcs(&src[tid]);
        *(float4*)(s + tid * 4) = v;
    }
    __syncthreads();
    g_xyz4[p0 + tid] = make_float4(s[tid * 3], s[tid * 3 + 1], s[tid * 3 + 2], 0.0f);
}

// ============ kT: transpose [B,32,M] -> [B,M,32], 32x128 tiles, f4 both sides ===
__global__ void __launch_bounds__(256) kT(
    const float* __restrict__ feat_pool,
    const float* __restrict__ feat_interp)
{
    __shared__ float sm[32 * 132];    // 32 rows x 132 floats (pad 4)
    int tid = threadIdx.x;
    int tb = blockIdx.x;
    const float* in;
    float* outp;
    int M;
    if (tb < TB1) { in = feat_pool;   outp = g_pool_t;   M = NN; }
    else          { in = feat_interp; outp = g_interp_t; M = NP; tb -= TB1; }
    int mb = M / 128;
    int b  = tb / mb;
    int m0 = (tb - b * mb) * 128;

    // load: tile[d][m] for d 0..31, m 0..127, float4 over m
    {
        int d  = tid >> 3;          // 0..31
        int cq = tid & 7;           // f4 col base
        const float4* row = (const float4*)(in + ((size_t)(b * DD + d)) * M + m0);
#pragma unroll
        for (int j = 0; j < 4; j++) {
            int c4 = cq + 8 * j;    // 0..31 f4 within row
            float4 v = __ldcs(&row[c4]);
            *(float4*)(sm + d * 132 + c4 * 4) = v;
        }
    }
    __syncthreads();
    // store: out rows m (128), each row 32 floats (8 f4)
    {
#pragma unroll
        for (int j = 0; j < 4; j++) {
            int idx = tid + 256 * j;       // 0..1023
            int m  = idx >> 3;             // 0..127
            int dq = idx & 7;              // f4 within d
            float4 v = make_float4(sm[(4 * dq + 0) * 132 + m],
                                   sm[(4 * dq + 1) * 132 + m],
                                   sm[(4 * dq + 2) * 132 + m],
                                   sm[(4 * dq + 3) * 132 + m]);
            // hmm: that's wrong orientation — tile is [d][m]; out[m][d] needs sm[d][m]
            ((float4*)(outp + ((size_t)(b * M + m0 + m)) * DD))[dq] = v;
        }
    }
}

// ============ kRel: 512 pairs/block, 2 pairs/thread, TMA bulk store ============
__global__ void __launch_bounds__(256) kRel(
    const int* __restrict__ nidx,
    float* __restrict__ out_rel)
{
    __shared__ __align__(16) float smem[5120];   // 20 KB
    int tid = threadIdx.x;
    int rb = blockIdx.x;                // 0..8191
    int pbase = rb * 512;
    int b   = pbase >> 20;              // N*K = 2^20
    int bb  = b << 16;
    int nkb = pbase & 0xFFFFF;
    int t2  = tid * 2;

    int2 ii = __ldcs((const int2*)(nidx + pbase + t2));
    float4 Q0 = __ldg(&g_xyz4[bb + ii.x]);
    float4 Q1 = __ldg(&g_xyz4[bb + ii.y]);
    // pairs (2t, 2t+1) share n since t2 is even and K=16
    float4 P  = __ldg(&g_xyz4[bb + ((nkb + t2) >> 4)]);

    float rx0 = P.x - Q0.x, ry0 = P.y - Q0.y, rz0 = P.z - Q0.z;
    float d0 = sqrtf(rx0 * rx0 + ry0 * ry0 + rz0 * rz0);
    float rx1 = P.x - Q1.x, ry1 = P.y - Q1.y, rz1 = P.z - Q1.z;
    float d1 = sqrtf(rx1 * rx1 + ry1 * ry1 + rz1 * rz1);

    float4* sp = (float4*)(smem + tid * 20);
    sp[0] = make_float4(d0, rx0, ry0, rz0);
    sp[1] = make_float4(P.x, P.y, P.z, Q0.x);
    sp[2] = make_float4(Q0.y, Q0.z, d1, rx1);
    sp[3] = make_float4(ry1, rz1, P.x, P.y);
    sp[4] = make_float4(P.z, Q1.x, Q1.y, Q1.z);
    __syncthreads();

    asm volatile("fence.proxy.async.shared::cta;" ::: "memory");
    if (tid == 0) {
        uint32_t sa = smem_u32(smem);
        float* gp = out_rel + (size_t)rb * 5120;
        asm volatile(
            "cp.async.bulk.global.shared::cta.bulk_group [%0], [%1], %2;"
            :: "l"(gp), "r"(sa), "n"(20480) : "memory");
        asm volatile("cp.async.bulk.commit_group;" ::: "memory");
        asm volatile("cp.async.bulk.wait_group.read 0;" ::: "memory");
    }
    __syncthreads();
}

// ============ kPI: pool + interp (bid&1) ============
__global__ void __launch_bounds__(256) kPI(
    const int* __restrict__ pool_idx,
    const int* __restrict__ interp_idx,
    float* __restrict__ out_pool,
    float* __restrict__ out_interp)
{
    __shared__ float smem[4 * 32 * 33];
    int bid = blockIdx.x;
    int tid = threadIdx.x;
    int lane = tid & 31, w = tid >> 5;
    int row  = w * 4 + (lane >> 3);
    int dv   = lane & 7;
    int r = bid & 1;
    int g = bid >> 1;

    if (r == 0) {
        // -------- gather-max pooling --------
        float (*tile)[33] = (float (*)[33])smem;
        int b   = g / (NP / 32);
        int np0 = (g - b * (NP / 32)) * 32;
        const int* ip = pool_idx + (b * NP + np0 + row) * KK;
        const float* basep = g_pool_t + (size_t)b * NN * DD;

        float4 m = make_float4(-INFINITY, -INFINITY, -INFINITY, -INFINITY);
#pragma unroll
        for (int kc = 0; kc < 4; kc++) {
            int4 q = __ldcs((const int4*)ip + kc);
            int qq[4] = {q.x, q.y, q.z, q.w};
#pragma unroll
            for (int j = 0; j < 4; j++) {
                float4 v = *(const float4*)(basep + qq[j] * DD + dv * 4);
                m.x = fmaxf(m.x, v.x); m.y = fmaxf(m.y, v.y);
                m.z = fmaxf(m.z, v.z); m.w = fmaxf(m.w, v.w);
            }
        }
        tile[row][dv * 4 + 0] = m.x;
        tile[row][dv * 4 + 1] = m.y;
        tile[row][dv * 4 + 2] = m.z;
        tile[row][dv * 4 + 3] = m.w;
        __syncthreads();
#pragma unroll
        for (int rr = 0; rr < 4; rr++) {
            int d = w + 8 * rr;
            __stcs(&out_pool[(size_t)(b * DD + d) * NP + np0 + lane], tile[lane][d]);
        }
    } else {
        // -------- nearest interpolation: 4 tiles / block --------
        float (*tile)[33] = (float (*)[33])smem;
        int b  = g / (NN / 128);
        int u0 = (g - b * (NN / 128)) * 128;

        float4 v[4];
#pragma unroll
        for (int it = 0; it < 4; it++) {
            int i = __ldg(&interp_idx[b * NN + u0 + it * 32 + row]);
            v[it] = *(const float4*)(g_interp_t + ((size_t)(b * NP + i)) * DD + dv * 4);
        }
#pragma unroll
        for (int it = 0; it < 4; it++) {
            tile[it * 32 + row][dv * 4 + 0] = v[it].x;
            tile[it * 32 + row][dv * 4 + 1] = v[it].y;
            tile[it * 32 + row][dv * 4 + 2] = v[it].z;
            tile[it * 32 + row][dv * 4 + 3] = v[it].w;
        }
        __syncthreads();
#pragma unroll
        for (int it = 0; it < 4; it++) {
#pragma unroll
            for (int rr = 0; rr < 4; rr++) {
                int d = w + 8 * rr;
                __stcs(&out_interp[(size_t)(b * DD + d) * NN + u0 + it * 32 + lane],
                       tile[it * 32 + lane][d]);
            }
        }
    }
}

extern "C" void kernel_launch(void* const* d_in, const int* in_sizes, int n_in,
                              void* d_out, int out_size) {
    const float* xyz         = (const float*)d_in[0];   // [B,N,3]
    const int*   neigh_idx   = (const int*)  d_in[1];   // [B,N,K]
    const float* feat_pool   = (const float*)d_in[2];   // [B,32,N,1]
    const int*   pool_idx    = (const int*)  d_in[3];   // [B,Np,K]
    const float* feat_interp = (const float*)d_in[4];   // [B,32,Np,1]
    const int*   interp_idx  = (const int*)  d_in[5];   // [B,N,1]

    float* out = (float*)d_out;
    float* out_rel    = out;                                // B*N*K*10
    float* out_pool   = out + (size_t)B * NN * KK * 10;     // B*32*Np
    float* out_interp = out_pool + (size_t)B * DD * NP;     // B*32*N

    // one-time side stream + events (host-side objects; no device allocs)
    static cudaStream_t s2 = nullptr;
    static cudaEvent_t evFork = nullptr, evJoin = nullptr;
    if (s2 == nullptr) {
        cudaStreamCreateWithFlags(&s2, cudaStreamNonBlocking);
        cudaEventCreateWithFlags(&evFork, cudaEventDisableTiming);
        cudaEventCreateWithFlags(&evJoin, cudaEventDisableTiming);
    }

    // fork: branch B (transposes -> pool/interp) runs parallel to branch A
    cudaEventRecord(evFork, 0);
    cudaStreamWaitEvent(s2, evFork, 0);

    // branch B on s2
    kT <<<TB1 + TB2, 256, 0, s2>>>(feat_pool, feat_interp);
    kPI<<<POOLB + IB4, 256, 0, s2>>>(pool_idx, interp_idx, out_pool, out_interp);
    cudaEventRecord(evJoin, s2);

    // branch A on default stream
    kX  <<<XB, 256>>>(xyz);
    kRel<<<RELB, 256>>>(neigh_idx, out_rel);

    // join
    cudaStreamWaitEvent(0, evJoin, 0);
}

// round 15
// speedup vs baseline: 1.0318x; 1.0039x over previous
#include <cuda_runtime.h>
#include <math.h>
#include <stdint.h>

#define B  4
#define NN 65536
#define KK 16
#define DD 32
#define NP 16384

// scratch
__device__ float  g_pool_t[(size_t)B * NN * DD];    // 33.6 MB  [b][n][d]
__device__ float  g_interp_t[(size_t)B * NP * DD];  //  8.4 MB  [b][np][d]
__device__ float4 g_xyz4[(size_t)B * NN];           //  4.2 MB  padded xyz

#define TB1   (B * (NN / 128))     // 2048  transpose feat_pool tiles (32x128)
#define TB2   (B * (NP / 128))     // 512   transpose feat_interp tiles
#define XB    (B * NN / 1024)      // 256   xyz padding blocks (1024 pts each)
#define RELB  (B * NN * KK / 1024) // 4096  rel blocks (1024 pairs each)
#define POOLB (B * (NP / 32))      // 2048  pool blocks
#define IB4   (B * (NN / 128))     // 2048  interp blocks (4 tiles each)

__device__ __forceinline__ uint32_t smem_u32(const void* p) {
    uint32_t a;
    asm("{ .reg .u64 t; cvta.to.shared.u64 t, %1; cvt.u32.u64 %0, t; }"
        : "=r"(a) : "l"(p));
    return a;
}

// ============ kX: pad xyz [B*N,3] -> float4, 1024 pts/block, MLP>=3 ============
__global__ void __launch_bounds__(256) kX(const float* __restrict__ xyz) {
    __shared__ float s[3072];
    int tid = threadIdx.x;
    int p0 = blockIdx.x * 1024;
    const float4* src = (const float4*)(xyz + (size_t)p0 * 3);  // 768 float4
#pragma unroll
    for (int j = 0; j < 3; j++) {
        float4 v = __ldcs(&src[j * 256 + tid]);
        *(float4*)(s + (j * 256 + tid) * 4) = v;
    }
    __syncthreads();
#pragma unroll
    for (int j = 0; j < 4; j++) {
        int p = j * 256 + tid;
        g_xyz4[p0 + p] = make_float4(s[p * 3], s[p * 3 + 1], s[p * 3 + 2], 0.0f);
    }
}

// ============ kT: transpose [B,32,M] -> [B,M,32], 32x128 tiles, f4 both sides ===
__global__ void __launch_bounds__(256) kT(
    const float* __restrict__ feat_pool,
    const float* __restrict__ feat_interp)
{
    __shared__ float sm[32 * 132];    // 32 rows x 132 floats (pad 4)
    int tid = threadIdx.x;
    int tb = blockIdx.x;
    const float* in;
    float* outp;
    int M;
    if (tb < TB1) { in = feat_pool;   outp = g_pool_t;   M = NN; }
    else          { in = feat_interp; outp = g_interp_t; M = NP; tb -= TB1; }
    int mb = M / 128;
    int b  = tb / mb;
    int m0 = (tb - b * mb) * 128;

    // load: tile[d][m] for d 0..31, m 0..127, float4 over m
    {
        int d  = tid >> 3;          // 0..31
        int cq = tid & 7;           // f4 col base
        const float4* row = (const float4*)(in + ((size_t)(b * DD + d)) * M + m0);
#pragma unroll
        for (int j = 0; j < 4; j++) {
            int c4 = cq + 8 * j;    // 0..31 f4 within row
            float4 v = __ldcs(&row[c4]);
            *(float4*)(sm + d * 132 + c4 * 4) = v;
        }
    }
    __syncthreads();
    // store: out rows m (128), each row 32 floats (8 f4); out[m][4dq..4dq+3] = tile[4dq..][m]
    {
#pragma unroll
        for (int j = 0; j < 4; j++) {
            int idx = tid + 256 * j;       // 0..1023
            int m  = idx >> 3;             // 0..127
            int dq = idx & 7;              // f4 within d
            float4 v = make_float4(sm[(4 * dq + 0) * 132 + m],
                                   sm[(4 * dq + 1) * 132 + m],
                                   sm[(4 * dq + 2) * 132 + m],
                                   sm[(4 * dq + 3) * 132 + m]);
            ((float4*)(outp + ((size_t)(b * M + m0 + m)) * DD))[dq] = v;
        }
    }
}

// ============ kRel: 1024 pairs/block, 512 threads, 40KB staging + TMA ============
__global__ void __launch_bounds__(512) kRel(
    const int* __restrict__ nidx,
    float* __restrict__ out_rel)
{
    __shared__ __align__(16) float smem[10240];   // 40 KB
    int tid = threadIdx.x;
    int rb = blockIdx.x;                // 0..4095
    int pbase = rb * 1024;
    int b   = pbase >> 20;              // N*K = 2^20
    int bb  = b << 16;
    int nkb = pbase & 0xFFFFF;
    int t2  = tid * 2;

    int2 ii = __ldcs((const int2*)(nidx + pbase + t2));
    float4 Q0 = __ldg(&g_xyz4[bb + ii.x]);
    float4 Q1 = __ldg(&g_xyz4[bb + ii.y]);
    // pairs (2t, 2t+1) share n since t2 is even and K=16
    float4 P  = __ldg(&g_xyz4[bb + ((nkb + t2) >> 4)]);

    float rx0 = P.x - Q0.x, ry0 = P.y - Q0.y, rz0 = P.z - Q0.z;
    float d0 = sqrtf(rx0 * rx0 + ry0 * ry0 + rz0 * rz0);
    float rx1 = P.x - Q1.x, ry1 = P.y - Q1.y, rz1 = P.z - Q1.z;
    float d1 = sqrtf(rx1 * rx1 + ry1 * ry1 + rz1 * rz1);

    float4* sp = (float4*)(smem + tid * 20);
    sp[0] = make_float4(d0, rx0, ry0, rz0);
    sp[1] = make_float4(P.x, P.y, P.z, Q0.x);
    sp[2] = make_float4(Q0.y, Q0.z, d1, rx1);
    sp[3] = make_float4(ry1, rz1, P.x, P.y);
    sp[4] = make_float4(P.z, Q1.x, Q1.y, Q1.z);
    __syncthreads();

    asm volatile("fence.proxy.async.shared::cta;" ::: "memory");
    if (tid == 0) {
        uint32_t sa = smem_u32(smem);
        float* gp = out_rel + (size_t)rb * 10240;
        asm volatile(
            "cp.async.bulk.global.shared::cta.bulk_group [%0], [%1], %2;"
            :: "l"(gp), "r"(sa), "n"(40960) : "memory");
        asm volatile("cp.async.bulk.commit_group;" ::: "memory");
        asm volatile("cp.async.bulk.wait_group.read 0;" ::: "memory");
    }
    __syncthreads();
}

// ============ kPI: pool + interp (bid&1) ============
__global__ void __launch_bounds__(256) kPI(
    const int* __restrict__ pool_idx,
    const int* __restrict__ interp_idx,
    float* __restrict__ out_pool,
    float* __restrict__ out_interp)
{
    __shared__ float smem[4 * 32 * 33];
    int bid = blockIdx.x;
    int tid = threadIdx.x;
    int lane = tid & 31, w = tid >> 5;
    int row  = w * 4 + (lane >> 3);
    int dv   = lane & 7;
    int r = bid & 1;
    int g = bid >> 1;

    if (r == 0) {
        // -------- gather-max pooling --------
        float (*tile)[33] = (float (*)[33])smem;
        int b   = g / (NP / 32);
        int np0 = (g - b * (NP / 32)) * 32;
        const int* ip = pool_idx + (b * NP + np0 + row) * KK;
        const float* basep = g_pool_t + (size_t)b * NN * DD;

        float4 m = make_float4(-INFINITY, -INFINITY, -INFINITY, -INFINITY);
#pragma unroll
        for (int kc = 0; kc < 4; kc++) {
            int4 q = __ldcs((const int4*)ip + kc);
            int qq[4] = {q.x, q.y, q.z, q.w};
#pragma unroll
            for (int j = 0; j < 4; j++) {
                float4 v = *(const float4*)(basep + qq[j] * DD + dv * 4);
                m.x = fmaxf(m.x, v.x); m.y = fmaxf(m.y, v.y);
                m.z = fmaxf(m.z, v.z); m.w = fmaxf(m.w, v.w);
            }
        }
        tile[row][dv * 4 + 0] = m.x;
        tile[row][dv * 4 + 1] = m.y;
        tile[row][dv * 4 + 2] = m.z;
        tile[row][dv * 4 + 3] = m.w;
        __syncthreads();
#pragma unroll
        for (int rr = 0; rr < 4; rr++) {
            int d = w + 8 * rr;
            __stcs(&out_pool[(size_t)(b * DD + d) * NP + np0 + lane], tile[lane][d]);
        }
    } else {
        // -------- nearest interpolation: 4 tiles / block --------
        float (*tile)[33] = (float (*)[33])smem;
        int b  = g / (NN / 128);
        int u0 = (g - b * (NN / 128)) * 128;

        float4 v[4];
#pragma unroll
        for (int it = 0; it < 4; it++) {
            int i = __ldg(&interp_idx[b * NN + u0 + it * 32 + row]);
            v[it] = *(const float4*)(g_interp_t + ((size_t)(b * NP + i)) * DD + dv * 4);
        }
#pragma unroll
        for (int it = 0; it < 4; it++) {
            tile[it * 32 + row][dv * 4 + 0] = v[it].x;
            tile[it * 32 + row][dv * 4 + 1] = v[it].y;
            tile[it * 32 + row][dv * 4 + 2] = v[it].z;
            tile[it * 32 + row][dv * 4 + 3] = v[it].w;
        }
        __syncthreads();
#pragma unroll
        for (int it = 0; it < 4; it++) {
#pragma unroll
            for (int rr = 0; rr < 4; rr++) {
                int d = w + 8 * rr;
                __stcs(&out_interp[(size_t)(b * DD + d) * NN + u0 + it * 32 + lane],
                       tile[it * 32 + lane][d]);
            }
        }
    }
}

extern "C" void kernel_launch(void* const* d_in, const int* in_sizes, int n_in,
                              void* d_out, int out_size) {
    const float* xyz         = (const float*)d_in[0];   // [B,N,3]
    const int*   neigh_idx   = (const int*)  d_in[1];   // [B,N,K]
    const float* feat_pool   = (const float*)d_in[2];   // [B,32,N,1]
    const int*   pool_idx    = (const int*)  d_in[3];   // [B,Np,K]
    const float* feat_interp = (const float*)d_in[4];   // [B,32,Np,1]
    const int*   interp_idx  = (const int*)  d_in[5];   // [B,N,1]

    float* out = (float*)d_out;
    float* out_rel    = out;                                // B*N*K*10
    float* out_pool   = out + (size_t)B * NN * KK * 10;     // B*32*Np
    float* out_interp = out_pool + (size_t)B * DD * NP;     // B*32*N

    // one-time side stream + events (host-side objects; no device allocs)
    static cudaStream_t s2 = nullptr;
    static cudaEvent_t evFork = nullptr, evJoin = nullptr;
    if (s2 == nullptr) {
        cudaStreamCreateWithFlags(&s2, cudaStreamNonBlocking);
        cudaEventCreateWithFlags(&evFork, cudaEventDisableTiming);
        cudaEventCreateWithFlags(&evJoin, cudaEventDisableTiming);
    }

    // fork: branch B (transposes -> pool/interp) runs parallel to branch A
    cudaEventRecord(evFork, 0);
    cudaStreamWaitEvent(s2, evFork, 0);

    // branch B on s2
    kT <<<TB1 + TB2, 256, 0, s2>>>(feat_pool, feat_interp);
    kPI<<<POOLB + IB4, 256, 0, s2>>>(pool_idx, interp_idx, out_pool, out_interp);
    cudaEventRecord(evJoin, s2);

    // branch A on default stream
    kX  <<<XB, 256>>>(xyz);
    kRel<<<RELB, 512>>>(neigh_idx, out_rel);

    // join
    cudaStreamWaitEvent(0, evJoin, 0);
}